// round 10
// baseline (speedup 1.0000x reference)
#include <cuda_runtime.h>
#include <stdint.h>

#define DEV_INLINE __device__ __forceinline__

// ---------------------------------------------------------------------------
// Common helpers
// ---------------------------------------------------------------------------

DEV_INLINE uint32_t f2tf32(float f) {
    uint32_t u;
    asm("cvt.rna.tf32.f32 %0, %1;" : "=r"(u) : "f"(f));
    return u;
}

// D = A(16x8, tf32, row) * B(8x8, tf32, col) + D, fp32 accumulate
DEV_INLINE void mma8(float* c, const uint32_t* a, uint32_t b0, uint32_t b1) {
    asm volatile(
        "mma.sync.aligned.m16n8k8.row.col.f32.tf32.tf32.f32 "
        "{%0,%1,%2,%3}, {%4,%5,%6,%7}, {%8,%9}, {%0,%1,%2,%3};\n"
        : "+f"(c[0]), "+f"(c[1]), "+f"(c[2]), "+f"(c[3])
        : "r"(a[0]), "r"(a[1]), "r"(a[2]), "r"(a[3]), "r"(b0), "r"(b1));
}

DEV_INLINE void cp16(uint32_t dst, const void* src) {
    asm volatile("cp.async.cg.shared.global [%0], [%1], 16;\n" :: "r"(dst), "l"(src));
}
DEV_INLINE void cp_commit() { asm volatile("cp.async.commit_group;\n" ::: "memory"); }
template <int N> DEV_INLINE void cp_wait() {
    asm volatile("cp.async.wait_group %0;\n" :: "n"(N) : "memory");
}

// ---------------------------------------------------------------------------
// Scratch (no cudaMalloc allowed)
// ---------------------------------------------------------------------------
__device__ float g_qkv[(size_t)4 * 2048 * 3072];   // [B*N, 3C]
__device__ float g_attn[(size_t)4 * 2048 * 1024];  // [B*N, C]

// ---------------------------------------------------------------------------
// GEMM: C[M,N] = A[M,K] @ B[N,K]^T (+ bias), tf32 tensor cores
// CTA tile 128x128, K-tile 16, 8 warps (2x4), warp tile 64x32
// ---------------------------------------------------------------------------
constexpr int BM = 128, BN = 128, BK = 16;
constexpr int GP = 20;  // shared pitch (floats): conflict-free quad fragment loads

template <bool BIAS>
__global__ void __launch_bounds__(256) gemm_kernel(
    const float* __restrict__ A, const float* __restrict__ B,
    const float* __restrict__ bias, float* __restrict__ C,
    int M, int N, int K)
{
    __shared__ float As[2][BM * GP];
    __shared__ float Bs[2][BN * GP];

    const int bm = blockIdx.y * BM;
    const int bn = blockIdx.x * BN;
    const int tid = threadIdx.x;
    const int lane = tid & 31;
    const int wid = tid >> 5;
    const int g = lane >> 2, tg = lane & 3;
    const int wm = (wid >> 2) * 64;  // warp row: 0 / 64
    const int wn = (wid & 3) * 32;   // warp col: 0/32/64/96

    // cooperative tile load indexing: each thread 1 float4 per 64-row half
    const int lrow = tid >> 2;        // 0..63
    const int lcol = (tid & 3) * 4;   // 0,4,8,12

    const float* Ag = A + (size_t)(bm + lrow) * K + lcol;
    const float* Bg = B + (size_t)(bn + lrow) * K + lcol;
    const uint32_t sA = (uint32_t)__cvta_generic_to_shared(&As[0][lrow * GP + lcol]);
    const uint32_t sB = (uint32_t)__cvta_generic_to_shared(&Bs[0][lrow * GP + lcol]);
    const uint32_t bufBytes = BM * GP * 4;
    const uint32_t rowHop = 64 * GP * 4;

    float acc[4][4][4];
    #pragma unroll
    for (int mt = 0; mt < 4; ++mt)
        #pragma unroll
        for (int nt = 0; nt < 4; ++nt)
            #pragma unroll
            for (int v = 0; v < 4; ++v)
                acc[mt][nt][v] = 0.f;

    const int KT = K / BK;

    // prefetch tile 0
    cp16(sA, Ag);
    cp16(sA + rowHop, Ag + (size_t)64 * K);
    cp16(sB, Bg);
    cp16(sB + rowHop, Bg + (size_t)64 * K);
    cp_commit();

    for (int kt = 0; kt < KT; ++kt) {
        if (kt + 1 < KT) {
            const float* a = Ag + (size_t)(kt + 1) * BK;
            const float* b = Bg + (size_t)(kt + 1) * BK;
            const uint32_t off = ((kt + 1) & 1) ? bufBytes : 0u;
            cp16(sA + off, a);
            cp16(sA + off + rowHop, a + (size_t)64 * K);
            cp16(sB + off, b);
            cp16(sB + off + rowHop, b + (size_t)64 * K);
            cp_commit();
            cp_wait<1>();   // tile kt arrived
        } else {
            cp_wait<0>();
        }
        __syncthreads();

        const float* as = As[kt & 1];
        const float* bs = Bs[kt & 1];
        #pragma unroll
        for (int ks = 0; ks < 2; ++ks) {
            const int ko = ks * 8;
            uint32_t af[4][4];
            #pragma unroll
            for (int mt = 0; mt < 4; ++mt) {
                const int r = wm + mt * 16 + g;
                af[mt][0] = f2tf32(as[r * GP + ko + tg]);
                af[mt][1] = f2tf32(as[(r + 8) * GP + ko + tg]);
                af[mt][2] = f2tf32(as[r * GP + ko + tg + 4]);
                af[mt][3] = f2tf32(as[(r + 8) * GP + ko + tg + 4]);
            }
            uint32_t bf[4][2];
            #pragma unroll
            for (int nt = 0; nt < 4; ++nt) {
                const int r = wn + nt * 8 + g;
                bf[nt][0] = f2tf32(bs[r * GP + ko + tg]);
                bf[nt][1] = f2tf32(bs[r * GP + ko + tg + 4]);
            }
            #pragma unroll
            for (int mt = 0; mt < 4; ++mt)
                #pragma unroll
                for (int nt = 0; nt < 4; ++nt)
                    mma8(acc[mt][nt], af[mt], bf[nt][0], bf[nt][1]);
        }
        __syncthreads();
    }

    // epilogue
    #pragma unroll
    for (int mt = 0; mt < 4; ++mt) {
        const int row = bm + wm + mt * 16 + g;
        #pragma unroll
        for (int nt = 0; nt < 4; ++nt) {
            const int col = bn + wn + nt * 8 + tg * 2;
            float2 v0 = make_float2(acc[mt][nt][0], acc[mt][nt][1]);
            float2 v1 = make_float2(acc[mt][nt][2], acc[mt][nt][3]);
            if (BIAS) {
                const float2 bb = *(const float2*)(bias + col);
                v0.x += bb.x; v0.y += bb.y;
                v1.x += bb.x; v1.y += bb.y;
            }
            *(float2*)(C + (size_t)row * N + col) = v0;
            *(float2*)(C + (size_t)(row + 8) * N + col) = v1;
        }
    }
}

// ---------------------------------------------------------------------------
// Flash attention: grid (32 q-blocks, 64 b*h), 128 threads (4 warps x 16 rows)
// BLOCK_M = BLOCK_N = 64, D = 64. tf32 mma; smem holds tf32 bits.
// ---------------------------------------------------------------------------
constexpr int SP = 68;  // shared pitch (u32): conflict-free B-fragment loads

__global__ void __launch_bounds__(128) attn_kernel(
    const float* __restrict__ qkv, float* __restrict__ out)
{
    extern __shared__ uint32_t sh[];
    uint32_t* QP = sh;                 // Q staging, then P staging (warp-private rows)
    uint32_t* Ks = sh + 64 * SP;
    uint32_t* Vs = sh + 2 * 64 * SP;

    const int bh = blockIdx.y;
    const int b = bh >> 4, h = bh & 15;
    const int qb = blockIdx.x;
    const int tid = threadIdx.x, w = tid >> 5, lane = tid & 31;
    const int g = lane >> 2, tg = lane & 3;

    const float* base = qkv + (size_t)b * 2048 * 3072 + h * 64;

    // Load Q tile [64][64], pre-scaled by 1/sqrt(D)=0.125, stored as tf32 bits
    for (int i = tid; i < 64 * 16; i += 128) {
        const int row = i >> 4, c4 = (i & 15) * 4;
        const float4 v = *(const float4*)(base + (size_t)(qb * 64 + row) * 3072 + c4);
        uint32_t* d = &QP[row * SP + c4];
        d[0] = f2tf32(v.x * 0.125f);
        d[1] = f2tf32(v.y * 0.125f);
        d[2] = f2tf32(v.z * 0.125f);
        d[3] = f2tf32(v.w * 0.125f);
    }
    __syncthreads();

    // Q A-fragments in registers: 8 k-tiles over D=64
    uint32_t qa[8][4];
    {
        const int r0 = (w * 16 + g) * SP, r1 = r0 + 8 * SP;
        #pragma unroll
        for (int ks = 0; ks < 8; ++ks) {
            qa[ks][0] = QP[r0 + ks * 8 + tg];
            qa[ks][1] = QP[r1 + ks * 8 + tg];
            qa[ks][2] = QP[r0 + ks * 8 + tg + 4];
            qa[ks][3] = QP[r1 + ks * 8 + tg + 4];
        }
    }

    float m0 = -1e30f, m1 = -1e30f, l0 = 0.f, l1 = 0.f;
    float o[8][4];
    #pragma unroll
    for (int nt = 0; nt < 8; ++nt) {
        o[nt][0] = o[nt][1] = o[nt][2] = o[nt][3] = 0.f;
    }

    const float* kb = base + 1024;
    const float* vb = base + 2048;

    for (int j = 0; j < 32; ++j) {
        __syncthreads();  // previous iteration done with Ks/Vs
        for (int i = tid; i < 64 * 16; i += 128) {
            const int row = i >> 4, c4 = (i & 15) * 4;
            const size_t go = (size_t)(j * 64 + row) * 3072 + c4;
            const float4 kv = *(const float4*)(kb + go);
            const float4 vv = *(const float4*)(vb + go);
            uint32_t* dk = &Ks[row * SP + c4];
            dk[0] = f2tf32(kv.x); dk[1] = f2tf32(kv.y);
            dk[2] = f2tf32(kv.z); dk[3] = f2tf32(kv.w);
            uint32_t* dv = &Vs[row * SP + c4];
            dv[0] = f2tf32(vv.x); dv[1] = f2tf32(vv.y);
            dv[2] = f2tf32(vv.z); dv[3] = f2tf32(vv.w);
        }
        __syncthreads();

        // S[16 x 64] = Q @ K^T   (K is B-operand, col-major: n = kv row, k = d)
        float s[8][4];
        #pragma unroll
        for (int nt = 0; nt < 8; ++nt) {
            s[nt][0] = s[nt][1] = s[nt][2] = s[nt][3] = 0.f;
            const int kr = (nt * 8 + g) * SP;
            #pragma unroll
            for (int ks = 0; ks < 8; ++ks)
                mma8(s[nt], qa[ks], Ks[kr + ks * 8 + tg], Ks[kr + ks * 8 + tg + 4]);
        }

        // Online softmax (rows g and g+8; quad-shuffle reductions)
        float tm0 = -1e30f, tm1 = -1e30f;
        #pragma unroll
        for (int nt = 0; nt < 8; ++nt) {
            tm0 = fmaxf(tm0, fmaxf(s[nt][0], s[nt][1]));
            tm1 = fmaxf(tm1, fmaxf(s[nt][2], s[nt][3]));
        }
        tm0 = fmaxf(tm0, __shfl_xor_sync(0xffffffffu, tm0, 1));
        tm0 = fmaxf(tm0, __shfl_xor_sync(0xffffffffu, tm0, 2));
        tm1 = fmaxf(tm1, __shfl_xor_sync(0xffffffffu, tm1, 1));
        tm1 = fmaxf(tm1, __shfl_xor_sync(0xffffffffu, tm1, 2));
        const float mn0 = fmaxf(m0, tm0), mn1 = fmaxf(m1, tm1);
        const float al0 = __expf(m0 - mn0), al1 = __expf(m1 - mn1);
        float rs0 = 0.f, rs1 = 0.f;
        #pragma unroll
        for (int nt = 0; nt < 8; ++nt) {
            s[nt][0] = __expf(s[nt][0] - mn0);
            s[nt][1] = __expf(s[nt][1] - mn0);
            s[nt][2] = __expf(s[nt][2] - mn1);
            s[nt][3] = __expf(s[nt][3] - mn1);
            rs0 += s[nt][0] + s[nt][1];
            rs1 += s[nt][2] + s[nt][3];
        }
        rs0 += __shfl_xor_sync(0xffffffffu, rs0, 1);
        rs0 += __shfl_xor_sync(0xffffffffu, rs0, 2);
        rs1 += __shfl_xor_sync(0xffffffffu, rs1, 1);
        rs1 += __shfl_xor_sync(0xffffffffu, rs1, 2);
        l0 = l0 * al0 + rs0;
        l1 = l1 * al1 + rs1;
        m0 = mn0; m1 = mn1;
        #pragma unroll
        for (int nt = 0; nt < 8; ++nt) {
            o[nt][0] *= al0; o[nt][1] *= al0;
            o[nt][2] *= al1; o[nt][3] *= al1;
        }

        // Re-fragment P: C-layout -> shared (warp-private rows) -> A-layout
        const int pr0 = (w * 16 + g) * SP, pr1 = pr0 + 8 * SP;
        #pragma unroll
        for (int nt = 0; nt < 8; ++nt) {
            const int c = nt * 8 + tg * 2;
            QP[pr0 + c]     = f2tf32(s[nt][0]);
            QP[pr0 + c + 1] = f2tf32(s[nt][1]);
            QP[pr1 + c]     = f2tf32(s[nt][2]);
            QP[pr1 + c + 1] = f2tf32(s[nt][3]);
        }
        __syncwarp();

        // O += P @ V  (V is B-operand, col-major: k = kv row, n = d)
        #pragma unroll
        for (int kt = 0; kt < 8; ++kt) {
            uint32_t pa[4];
            pa[0] = QP[pr0 + kt * 8 + tg];
            pa[1] = QP[pr1 + kt * 8 + tg];
            pa[2] = QP[pr0 + kt * 8 + tg + 4];
            pa[3] = QP[pr1 + kt * 8 + tg + 4];
            const int vr0 = (kt * 8 + tg) * SP;
            const int vr1 = (kt * 8 + tg + 4) * SP;
            #pragma unroll
            for (int nt = 0; nt < 8; ++nt)
                mma8(o[nt], pa, Vs[vr0 + nt * 8 + g], Vs[vr1 + nt * 8 + g]);
        }
    }

    // Epilogue: normalize and write [b, n, h*64 + d]
    const float il0 = 1.f / l0, il1 = 1.f / l1;
    const int r0 = qb * 64 + w * 16 + g;
    float* ob = g_attn + ((size_t)b * 2048 + r0) * 1024 + h * 64;
    (void)out;
    #pragma unroll
    for (int nt = 0; nt < 8; ++nt) {
        const int c = nt * 8 + tg * 2;
        *(float2*)(ob + c) = make_float2(o[nt][0] * il0, o[nt][1] * il0);
        *(float2*)(ob + (size_t)8 * 1024 + c) = make_float2(o[nt][2] * il1, o[nt][3] * il1);
    }
}

// ---------------------------------------------------------------------------
// Launch
// ---------------------------------------------------------------------------
extern "C" void kernel_launch(void* const* d_in, const int* in_sizes, int n_in,
                              void* d_out, int out_size)
{
    const float *x = nullptr, *wqkv = nullptr, *wproj = nullptr, *bias = nullptr;
    for (int i = 0; i < n_in; ++i) {
        switch (in_sizes[i]) {
            case 4 * 2048 * 1024: x     = (const float*)d_in[i]; break;  // 8388608
            case 3 * 1024 * 1024: wqkv  = (const float*)d_in[i]; break;  // 3145728
            case 1024 * 1024:     wproj = (const float*)d_in[i]; break;  // 1048576
            case 1024:            bias  = (const float*)d_in[i]; break;
        }
    }
    if (!x || !wqkv || !wproj || !bias) {  // positional fallback
        x = (const float*)d_in[0];
        wqkv = (const float*)d_in[1];
        wproj = (const float*)d_in[2];
        bias = (const float*)d_in[3];
    }

    float *qkv_buf, *attn_buf;
    cudaGetSymbolAddress((void**)&qkv_buf, g_qkv);
    cudaGetSymbolAddress((void**)&attn_buf, g_attn);
    float* out = (float*)d_out;

    constexpr int M = 4 * 2048;  // 8192 tokens

    // 1) qkv = x @ W_qkv^T   [8192, 3072]
    gemm_kernel<false><<<dim3(3072 / BN, M / BM), 256>>>(
        x, wqkv, nullptr, qkv_buf, M, 3072, 1024);

    // 2) flash attention -> g_attn [8192, 1024]
    const int smem = 3 * 64 * SP * 4;  // 52224 bytes
    cudaFuncSetAttribute(attn_kernel, cudaFuncAttributeMaxDynamicSharedMemorySize, smem);
    attn_kernel<<<dim3(32, 64), 128, smem>>>(qkv_buf, attn_buf);

    // 3) out = attn @ W_proj^T + b
    gemm_kernel<true><<<dim3(1024 / BN, M / BM), 256>>>(
        attn_buf, wproj, bias, out, M, 1024, 1024);
    (void)out_size;
}

// round 11
// speedup vs baseline: 1.0012x; 1.0012x over previous
#include <cuda_runtime.h>
#include <stdint.h>

#define DEV_INLINE __device__ __forceinline__

// ---------------------------------------------------------------------------
// Common helpers
// ---------------------------------------------------------------------------

DEV_INLINE uint32_t f2tf32(float f) {
    uint32_t u;
    asm("cvt.rna.tf32.f32 %0, %1;" : "=r"(u) : "f"(f));
    return u;
}

// D = A(16x8, tf32, row) * B(8x8, tf32, col) + D, fp32 accumulate
DEV_INLINE void mma8(float* c, const uint32_t* a, uint32_t b0, uint32_t b1) {
    asm volatile(
        "mma.sync.aligned.m16n8k8.row.col.f32.tf32.tf32.f32 "
        "{%0,%1,%2,%3}, {%4,%5,%6,%7}, {%8,%9}, {%0,%1,%2,%3};\n"
        : "+f"(c[0]), "+f"(c[1]), "+f"(c[2]), "+f"(c[3])
        : "r"(a[0]), "r"(a[1]), "r"(a[2]), "r"(a[3]), "r"(b0), "r"(b1));
}

DEV_INLINE void cp16(uint32_t dst, const void* src) {
    asm volatile("cp.async.cg.shared.global [%0], [%1], 16;\n" :: "r"(dst), "l"(src));
}
DEV_INLINE void cp_commit() { asm volatile("cp.async.commit_group;\n" ::: "memory"); }
template <int N> DEV_INLINE void cp_wait() {
    asm volatile("cp.async.wait_group %0;\n" :: "n"(N) : "memory");
}

// ---------------------------------------------------------------------------
// Scratch (no cudaMalloc allowed)
// ---------------------------------------------------------------------------
__device__ float g_qkv[(size_t)4 * 2048 * 3072];   // [B*N, 3C]
__device__ float g_attn[(size_t)4 * 2048 * 1024];  // [B*N, C]

// ---------------------------------------------------------------------------
// GEMM: C[M,N] = A[M,K] @ B[N,K]^T (+ bias), tf32 tensor cores
// CTA tile 128x128, K-tile 16, 8 warps (2x4), warp tile 64x32
// ---------------------------------------------------------------------------
constexpr int BM = 128, BN = 128, BK = 16;
constexpr int GP = 20;  // shared pitch (floats): conflict-free quad fragment loads

template <bool BIAS>
__global__ void __launch_bounds__(256) gemm_kernel(
    const float* __restrict__ A, const float* __restrict__ B,
    const float* __restrict__ bias, float* __restrict__ C,
    int M, int N, int K)
{
    __shared__ float As[2][BM * GP];
    __shared__ float Bs[2][BN * GP];

    const int bm = blockIdx.y * BM;
    const int bn = blockIdx.x * BN;
    const int tid = threadIdx.x;
    const int lane = tid & 31;
    const int wid = tid >> 5;
    const int g = lane >> 2, tg = lane & 3;
    const int wm = (wid >> 2) * 64;  // warp row: 0 / 64
    const int wn = (wid & 3) * 32;   // warp col: 0/32/64/96

    // cooperative tile load indexing: each thread 1 float4 per 64-row half
    const int lrow = tid >> 2;        // 0..63
    const int lcol = (tid & 3) * 4;   // 0,4,8,12

    const float* Ag = A + (size_t)(bm + lrow) * K + lcol;
    const float* Bg = B + (size_t)(bn + lrow) * K + lcol;
    const uint32_t sA = (uint32_t)__cvta_generic_to_shared(&As[0][lrow * GP + lcol]);
    const uint32_t sB = (uint32_t)__cvta_generic_to_shared(&Bs[0][lrow * GP + lcol]);
    const uint32_t bufBytes = BM * GP * 4;
    const uint32_t rowHop = 64 * GP * 4;

    float acc[4][4][4];
    #pragma unroll
    for (int mt = 0; mt < 4; ++mt)
        #pragma unroll
        for (int nt = 0; nt < 4; ++nt)
            #pragma unroll
            for (int v = 0; v < 4; ++v)
                acc[mt][nt][v] = 0.f;

    const int KT = K / BK;

    // prefetch tile 0
    cp16(sA, Ag);
    cp16(sA + rowHop, Ag + (size_t)64 * K);
    cp16(sB, Bg);
    cp16(sB + rowHop, Bg + (size_t)64 * K);
    cp_commit();

    for (int kt = 0; kt < KT; ++kt) {
        if (kt + 1 < KT) {
            const float* a = Ag + (size_t)(kt + 1) * BK;
            const float* b = Bg + (size_t)(kt + 1) * BK;
            const uint32_t off = ((kt + 1) & 1) ? bufBytes : 0u;
            cp16(sA + off, a);
            cp16(sA + off + rowHop, a + (size_t)64 * K);
            cp16(sB + off, b);
            cp16(sB + off + rowHop, b + (size_t)64 * K);
            cp_commit();
            cp_wait<1>();   // tile kt arrived
        } else {
            cp_wait<0>();
        }
        __syncthreads();

        const float* as = As[kt & 1];
        const float* bs = Bs[kt & 1];
        #pragma unroll
        for (int ks = 0; ks < 2; ++ks) {
            const int ko = ks * 8;
            uint32_t af[4][4];
            #pragma unroll
            for (int mt = 0; mt < 4; ++mt) {
                const int r = wm + mt * 16 + g;
                af[mt][0] = f2tf32(as[r * GP + ko + tg]);
                af[mt][1] = f2tf32(as[(r + 8) * GP + ko + tg]);
                af[mt][2] = f2tf32(as[r * GP + ko + tg + 4]);
                af[mt][3] = f2tf32(as[(r + 8) * GP + ko + tg + 4]);
            }
            uint32_t bf[4][2];
            #pragma unroll
            for (int nt = 0; nt < 4; ++nt) {
                const int r = wn + nt * 8 + g;
                bf[nt][0] = f2tf32(bs[r * GP + ko + tg]);
                bf[nt][1] = f2tf32(bs[r * GP + ko + tg + 4]);
            }
            #pragma unroll
            for (int mt = 0; mt < 4; ++mt)
                #pragma unroll
                for (int nt = 0; nt < 4; ++nt)
                    mma8(acc[mt][nt], af[mt], bf[nt][0], bf[nt][1]);
        }
        __syncthreads();
    }

    // epilogue
    #pragma unroll
    for (int mt = 0; mt < 4; ++mt) {
        const int row = bm + wm + mt * 16 + g;
        #pragma unroll
        for (int nt = 0; nt < 4; ++nt) {
            const int col = bn + wn + nt * 8 + tg * 2;
            float2 v0 = make_float2(acc[mt][nt][0], acc[mt][nt][1]);
            float2 v1 = make_float2(acc[mt][nt][2], acc[mt][nt][3]);
            if (BIAS) {
                const float2 bb = *(const float2*)(bias + col);
                v0.x += bb.x; v0.y += bb.y;
                v1.x += bb.x; v1.y += bb.y;
            }
            *(float2*)(C + (size_t)row * N + col) = v0;
            *(float2*)(C + (size_t)(row + 8) * N + col) = v1;
        }
    }
}

// ---------------------------------------------------------------------------
// Flash attention: grid (32 q-blocks, 64 b*h), 128 threads (4 warps x 16 rows)
// BLOCK_M = BLOCK_N = 64, D = 64. tf32 mma; smem holds tf32 bits.
// ---------------------------------------------------------------------------
constexpr int SP = 68;  // shared pitch (u32): conflict-free B-fragment loads

__global__ void __launch_bounds__(128) attn_kernel(
    const float* __restrict__ qkv, float* __restrict__ out)
{
    extern __shared__ uint32_t sh[];
    uint32_t* QP = sh;                 // Q staging, then P staging (warp-private rows)
    uint32_t* Ks = sh + 64 * SP;
    uint32_t* Vs = sh + 2 * 64 * SP;

    const int bh = blockIdx.y;
    const int b = bh >> 4, h = bh & 15;
    const int qb = blockIdx.x;
    const int tid = threadIdx.x, w = tid >> 5, lane = tid & 31;
    const int g = lane >> 2, tg = lane & 3;

    const float* base = qkv + (size_t)b * 2048 * 3072 + h * 64;

    // Load Q tile [64][64], pre-scaled by 1/sqrt(D)=0.125, stored as tf32 bits
    for (int i = tid; i < 64 * 16; i += 128) {
        const int row = i >> 4, c4 = (i & 15) * 4;
        const float4 v = *(const float4*)(base + (size_t)(qb * 64 + row) * 3072 + c4);
        uint32_t* d = &QP[row * SP + c4];
        d[0] = f2tf32(v.x * 0.125f);
        d[1] = f2tf32(v.y * 0.125f);
        d[2] = f2tf32(v.z * 0.125f);
        d[3] = f2tf32(v.w * 0.125f);
    }
    __syncthreads();

    // Q A-fragments in registers: 8 k-tiles over D=64
    uint32_t qa[8][4];
    {
        const int r0 = (w * 16 + g) * SP, r1 = r0 + 8 * SP;
        #pragma unroll
        for (int ks = 0; ks < 8; ++ks) {
            qa[ks][0] = QP[r0 + ks * 8 + tg];
            qa[ks][1] = QP[r1 + ks * 8 + tg];
            qa[ks][2] = QP[r0 + ks * 8 + tg + 4];
            qa[ks][3] = QP[r1 + ks * 8 + tg + 4];
        }
    }

    float m0 = -1e30f, m1 = -1e30f, l0 = 0.f, l1 = 0.f;
    float o[8][4];
    #pragma unroll
    for (int nt = 0; nt < 8; ++nt) {
        o[nt][0] = o[nt][1] = o[nt][2] = o[nt][3] = 0.f;
    }

    const float* kb = base + 1024;
    const float* vb = base + 2048;

    for (int j = 0; j < 32; ++j) {
        __syncthreads();  // previous iteration done with Ks/Vs
        for (int i = tid; i < 64 * 16; i += 128) {
            const int row = i >> 4, c4 = (i & 15) * 4;
            const size_t go = (size_t)(j * 64 + row) * 3072 + c4;
            const float4 kv = *(const float4*)(kb + go);
            const float4 vv = *(const float4*)(vb + go);
            uint32_t* dk = &Ks[row * SP + c4];
            dk[0] = f2tf32(kv.x); dk[1] = f2tf32(kv.y);
            dk[2] = f2tf32(kv.z); dk[3] = f2tf32(kv.w);
            uint32_t* dv = &Vs[row * SP + c4];
            dv[0] = f2tf32(vv.x); dv[1] = f2tf32(vv.y);
            dv[2] = f2tf32(vv.z); dv[3] = f2tf32(vv.w);
        }
        __syncthreads();

        // S[16 x 64] = Q @ K^T   (K is B-operand, col-major: n = kv row, k = d)
        float s[8][4];
        #pragma unroll
        for (int nt = 0; nt < 8; ++nt) {
            s[nt][0] = s[nt][1] = s[nt][2] = s[nt][3] = 0.f;
            const int kr = (nt * 8 + g) * SP;
            #pragma unroll
            for (int ks = 0; ks < 8; ++ks)
                mma8(s[nt], qa[ks], Ks[kr + ks * 8 + tg], Ks[kr + ks * 8 + tg + 4]);
        }

        // Online softmax (rows g and g+8; quad-shuffle reductions)
        float tm0 = -1e30f, tm1 = -1e30f;
        #pragma unroll
        for (int nt = 0; nt < 8; ++nt) {
            tm0 = fmaxf(tm0, fmaxf(s[nt][0], s[nt][1]));
            tm1 = fmaxf(tm1, fmaxf(s[nt][2], s[nt][3]));
        }
        tm0 = fmaxf(tm0, __shfl_xor_sync(0xffffffffu, tm0, 1));
        tm0 = fmaxf(tm0, __shfl_xor_sync(0xffffffffu, tm0, 2));
        tm1 = fmaxf(tm1, __shfl_xor_sync(0xffffffffu, tm1, 1));
        tm1 = fmaxf(tm1, __shfl_xor_sync(0xffffffffu, tm1, 2));
        const float mn0 = fmaxf(m0, tm0), mn1 = fmaxf(m1, tm1);
        const float al0 = __expf(m0 - mn0), al1 = __expf(m1 - mn1);
        float rs0 = 0.f, rs1 = 0.f;
        #pragma unroll
        for (int nt = 0; nt < 8; ++nt) {
            s[nt][0] = __expf(s[nt][0] - mn0);
            s[nt][1] = __expf(s[nt][1] - mn0);
            s[nt][2] = __expf(s[nt][2] - mn1);
            s[nt][3] = __expf(s[nt][3] - mn1);
            rs0 += s[nt][0] + s[nt][1];
            rs1 += s[nt][2] + s[nt][3];
        }
        rs0 += __shfl_xor_sync(0xffffffffu, rs0, 1);
        rs0 += __shfl_xor_sync(0xffffffffu, rs0, 2);
        rs1 += __shfl_xor_sync(0xffffffffu, rs1, 1);
        rs1 += __shfl_xor_sync(0xffffffffu, rs1, 2);
        l0 = l0 * al0 + rs0;
        l1 = l1 * al1 + rs1;
        m0 = mn0; m1 = mn1;
        #pragma unroll
        for (int nt = 0; nt < 8; ++nt) {
            o[nt][0] *= al0; o[nt][1] *= al0;
            o[nt][2] *= al1; o[nt][3] *= al1;
        }

        // Re-fragment P: C-layout -> shared (warp-private rows) -> A-layout
        const int pr0 = (w * 16 + g) * SP, pr1 = pr0 + 8 * SP;
        #pragma unroll
        for (int nt = 0; nt < 8; ++nt) {
            const int c = nt * 8 + tg * 2;
            QP[pr0 + c]     = f2tf32(s[nt][0]);
            QP[pr0 + c + 1] = f2tf32(s[nt][1]);
            QP[pr1 + c]     = f2tf32(s[nt][2]);
            QP[pr1 + c + 1] = f2tf32(s[nt][3]);
        }
        __syncwarp();

        // O += P @ V  (V is B-operand, col-major: k = kv row, n = d)
        #pragma unroll
        for (int kt = 0; kt < 8; ++kt) {
            uint32_t pa[4];
            pa[0] = QP[pr0 + kt * 8 + tg];
            pa[1] = QP[pr1 + kt * 8 + tg];
            pa[2] = QP[pr0 + kt * 8 + tg + 4];
            pa[3] = QP[pr1 + kt * 8 + tg + 4];
            const int vr0 = (kt * 8 + tg) * SP;
            const int vr1 = (kt * 8 + tg + 4) * SP;
            #pragma unroll
            for (int nt = 0; nt < 8; ++nt)
                mma8(o[nt], pa, Vs[vr0 + nt * 8 + g], Vs[vr1 + nt * 8 + g]);
        }
    }

    // Epilogue: normalize and write [b, n, h*64 + d]
    const float il0 = 1.f / l0, il1 = 1.f / l1;
    const int r0 = qb * 64 + w * 16 + g;
    float* ob = g_attn + ((size_t)b * 2048 + r0) * 1024 + h * 64;
    (void)out;
    #pragma unroll
    for (int nt = 0; nt < 8; ++nt) {
        const int c = nt * 8 + tg * 2;
        *(float2*)(ob + c) = make_float2(o[nt][0] * il0, o[nt][1] * il0);
        *(float2*)(ob + (size_t)8 * 1024 + c) = make_float2(o[nt][2] * il1, o[nt][3] * il1);
    }
}

// ---------------------------------------------------------------------------
// Launch
// ---------------------------------------------------------------------------
extern "C" void kernel_launch(void* const* d_in, const int* in_sizes, int n_in,
                              void* d_out, int out_size)
{
    const float *x = nullptr, *wqkv = nullptr, *wproj = nullptr, *bias = nullptr;
    for (int i = 0; i < n_in; ++i) {
        switch (in_sizes[i]) {
            case 4 * 2048 * 1024: x     = (const float*)d_in[i]; break;  // 8388608
            case 3 * 1024 * 1024: wqkv  = (const float*)d_in[i]; break;  // 3145728
            case 1024 * 1024:     wproj = (const float*)d_in[i]; break;  // 1048576
            case 1024:            bias  = (const float*)d_in[i]; break;
        }
    }
    if (!x || !wqkv || !wproj || !bias) {  // positional fallback
        x = (const float*)d_in[0];
        wqkv = (const float*)d_in[1];
        wproj = (const float*)d_in[2];
        bias = (const float*)d_in[3];
    }

    float *qkv_buf, *attn_buf;
    cudaGetSymbolAddress((void**)&qkv_buf, g_qkv);
    cudaGetSymbolAddress((void**)&attn_buf, g_attn);
    float* out = (float*)d_out;

    constexpr int M = 4 * 2048;  // 8192 tokens

    // 1) qkv = x @ W_qkv^T   [8192, 3072]
    gemm_kernel<false><<<dim3(3072 / BN, M / BM), 256>>>(
        x, wqkv, nullptr, qkv_buf, M, 3072, 1024);

    // 2) flash attention -> g_attn [8192, 1024]
    const int smem = 3 * 64 * SP * 4;  // 52224 bytes
    cudaFuncSetAttribute(attn_kernel, cudaFuncAttributeMaxDynamicSharedMemorySize, smem);
    attn_kernel<<<dim3(32, 64), 128, smem>>>(qkv_buf, attn_buf);

    // 3) out = attn @ W_proj^T + b
    gemm_kernel<true><<<dim3(1024 / BN, M / BM), 256>>>(
        attn_buf, wproj, bias, out, M, 1024, 1024);
    (void)out_size;
}

// round 12
// speedup vs baseline: 1.0014x; 1.0002x over previous
#include <cuda_runtime.h>
#include <stdint.h>

#define DEV_INLINE __device__ __forceinline__

// ---------------------------------------------------------------------------
// Common helpers
// ---------------------------------------------------------------------------

DEV_INLINE uint32_t f2tf32(float f) {
    uint32_t u;
    asm("cvt.rna.tf32.f32 %0, %1;" : "=r"(u) : "f"(f));
    return u;
}

// D = A(16x8, tf32, row) * B(8x8, tf32, col) + D, fp32 accumulate
DEV_INLINE void mma8(float* c, const uint32_t* a, uint32_t b0, uint32_t b1) {
    asm volatile(
        "mma.sync.aligned.m16n8k8.row.col.f32.tf32.tf32.f32 "
        "{%0,%1,%2,%3}, {%4,%5,%6,%7}, {%8,%9}, {%0,%1,%2,%3};\n"
        : "+f"(c[0]), "+f"(c[1]), "+f"(c[2]), "+f"(c[3])
        : "r"(a[0]), "r"(a[1]), "r"(a[2]), "r"(a[3]), "r"(b0), "r"(b1));
}

DEV_INLINE void cp16(uint32_t dst, const void* src) {
    asm volatile("cp.async.cg.shared.global [%0], [%1], 16;\n" :: "r"(dst), "l"(src));
}
DEV_INLINE void cp_commit() { asm volatile("cp.async.commit_group;\n" ::: "memory"); }
template <int N> DEV_INLINE void cp_wait() {
    asm volatile("cp.async.wait_group %0;\n" :: "n"(N) : "memory");
}

// ---------------------------------------------------------------------------
// Scratch (no cudaMalloc allowed)
// ---------------------------------------------------------------------------
__device__ float g_qkv[(size_t)4 * 2048 * 3072];   // [B*N, 3C]
__device__ float g_attn[(size_t)4 * 2048 * 1024];  // [B*N, C]

// ---------------------------------------------------------------------------
// GEMM: C[M,N] = A[M,K] @ B[N,K]^T (+ bias), tf32 tensor cores
// CTA tile 128x128, K-tile 16, 8 warps (2x4), warp tile 64x32
// ---------------------------------------------------------------------------
constexpr int BM = 128, BN = 128, BK = 16;
constexpr int GP = 20;  // shared pitch (floats): conflict-free quad fragment loads

template <bool BIAS>
__global__ void __launch_bounds__(256) gemm_kernel(
    const float* __restrict__ A, const float* __restrict__ B,
    const float* __restrict__ bias, float* __restrict__ C,
    int M, int N, int K)
{
    __shared__ float As[2][BM * GP];
    __shared__ float Bs[2][BN * GP];

    const int bm = blockIdx.y * BM;
    const int bn = blockIdx.x * BN;
    const int tid = threadIdx.x;
    const int lane = tid & 31;
    const int wid = tid >> 5;
    const int g = lane >> 2, tg = lane & 3;
    const int wm = (wid >> 2) * 64;  // warp row: 0 / 64
    const int wn = (wid & 3) * 32;   // warp col: 0/32/64/96

    // cooperative tile load indexing: each thread 1 float4 per 64-row half
    const int lrow = tid >> 2;        // 0..63
    const int lcol = (tid & 3) * 4;   // 0,4,8,12

    const float* Ag = A + (size_t)(bm + lrow) * K + lcol;
    const float* Bg = B + (size_t)(bn + lrow) * K + lcol;
    const uint32_t sA = (uint32_t)__cvta_generic_to_shared(&As[0][lrow * GP + lcol]);
    const uint32_t sB = (uint32_t)__cvta_generic_to_shared(&Bs[0][lrow * GP + lcol]);
    const uint32_t bufBytes = BM * GP * 4;
    const uint32_t rowHop = 64 * GP * 4;

    float acc[4][4][4];
    #pragma unroll
    for (int mt = 0; mt < 4; ++mt)
        #pragma unroll
        for (int nt = 0; nt < 4; ++nt)
            #pragma unroll
            for (int v = 0; v < 4; ++v)
                acc[mt][nt][v] = 0.f;

    const int KT = K / BK;

    // prefetch tile 0
    cp16(sA, Ag);
    cp16(sA + rowHop, Ag + (size_t)64 * K);
    cp16(sB, Bg);
    cp16(sB + rowHop, Bg + (size_t)64 * K);
    cp_commit();

    for (int kt = 0; kt < KT; ++kt) {
        if (kt + 1 < KT) {
            const float* a = Ag + (size_t)(kt + 1) * BK;
            const float* b = Bg + (size_t)(kt + 1) * BK;
            const uint32_t off = ((kt + 1) & 1) ? bufBytes : 0u;
            cp16(sA + off, a);
            cp16(sA + off + rowHop, a + (size_t)64 * K);
            cp16(sB + off, b);
            cp16(sB + off + rowHop, b + (size_t)64 * K);
            cp_commit();
            cp_wait<1>();   // tile kt arrived
        } else {
            cp_wait<0>();
        }
        __syncthreads();

        const float* as = As[kt & 1];
        const float* bs = Bs[kt & 1];
        #pragma unroll
        for (int ks = 0; ks < 2; ++ks) {
            const int ko = ks * 8;
            uint32_t af[4][4];
            #pragma unroll
            for (int mt = 0; mt < 4; ++mt) {
                const int r = wm + mt * 16 + g;
                af[mt][0] = f2tf32(as[r * GP + ko + tg]);
                af[mt][1] = f2tf32(as[(r + 8) * GP + ko + tg]);
                af[mt][2] = f2tf32(as[r * GP + ko + tg + 4]);
                af[mt][3] = f2tf32(as[(r + 8) * GP + ko + tg + 4]);
            }
            uint32_t bf[4][2];
            #pragma unroll
            for (int nt = 0; nt < 4; ++nt) {
                const int r = wn + nt * 8 + g;
                bf[nt][0] = f2tf32(bs[r * GP + ko + tg]);
                bf[nt][1] = f2tf32(bs[r * GP + ko + tg + 4]);
            }
            #pragma unroll
            for (int mt = 0; mt < 4; ++mt)
                #pragma unroll
                for (int nt = 0; nt < 4; ++nt)
                    mma8(acc[mt][nt], af[mt], bf[nt][0], bf[nt][1]);
        }
        __syncthreads();
    }

    // epilogue
    #pragma unroll
    for (int mt = 0; mt < 4; ++mt) {
        const int row = bm + wm + mt * 16 + g;
        #pragma unroll
        for (int nt = 0; nt < 4; ++nt) {
            const int col = bn + wn + nt * 8 + tg * 2;
            float2 v0 = make_float2(acc[mt][nt][0], acc[mt][nt][1]);
            float2 v1 = make_float2(acc[mt][nt][2], acc[mt][nt][3]);
            if (BIAS) {
                const float2 bb = *(const float2*)(bias + col);
                v0.x += bb.x; v0.y += bb.y;
                v1.x += bb.x; v1.y += bb.y;
            }
            *(float2*)(C + (size_t)row * N + col) = v0;
            *(float2*)(C + (size_t)(row + 8) * N + col) = v1;
        }
    }
}

// ---------------------------------------------------------------------------
// Flash attention: grid (32 q-blocks, 64 b*h), 128 threads (4 warps x 16 rows)
// BLOCK_M = BLOCK_N = 64, D = 64. tf32 mma; smem holds tf32 bits.
// ---------------------------------------------------------------------------
constexpr int SP = 68;  // shared pitch (u32): conflict-free B-fragment loads

__global__ void __launch_bounds__(128) attn_kernel(
    const float* __restrict__ qkv, float* __restrict__ out)
{
    extern __shared__ uint32_t sh[];
    uint32_t* QP = sh;                 // Q staging, then P staging (warp-private rows)
    uint32_t* Ks = sh + 64 * SP;
    uint32_t* Vs = sh + 2 * 64 * SP;

    const int bh = blockIdx.y;
    const int b = bh >> 4, h = bh & 15;
    const int qb = blockIdx.x;
    const int tid = threadIdx.x, w = tid >> 5, lane = tid & 31;
    const int g = lane >> 2, tg = lane & 3;

    const float* base = qkv + (size_t)b * 2048 * 3072 + h * 64;

    // Load Q tile [64][64], pre-scaled by 1/sqrt(D)=0.125, stored as tf32 bits
    for (int i = tid; i < 64 * 16; i += 128) {
        const int row = i >> 4, c4 = (i & 15) * 4;
        const float4 v = *(const float4*)(base + (size_t)(qb * 64 + row) * 3072 + c4);
        uint32_t* d = &QP[row * SP + c4];
        d[0] = f2tf32(v.x * 0.125f);
        d[1] = f2tf32(v.y * 0.125f);
        d[2] = f2tf32(v.z * 0.125f);
        d[3] = f2tf32(v.w * 0.125f);
    }
    __syncthreads();

    // Q A-fragments in registers: 8 k-tiles over D=64
    uint32_t qa[8][4];
    {
        const int r0 = (w * 16 + g) * SP, r1 = r0 + 8 * SP;
        #pragma unroll
        for (int ks = 0; ks < 8; ++ks) {
            qa[ks][0] = QP[r0 + ks * 8 + tg];
            qa[ks][1] = QP[r1 + ks * 8 + tg];
            qa[ks][2] = QP[r0 + ks * 8 + tg + 4];
            qa[ks][3] = QP[r1 + ks * 8 + tg + 4];
        }
    }

    float m0 = -1e30f, m1 = -1e30f, l0 = 0.f, l1 = 0.f;
    float o[8][4];
    #pragma unroll
    for (int nt = 0; nt < 8; ++nt) {
        o[nt][0] = o[nt][1] = o[nt][2] = o[nt][3] = 0.f;
    }

    const float* kb = base + 1024;
    const float* vb = base + 2048;

    for (int j = 0; j < 32; ++j) {
        __syncthreads();  // previous iteration done with Ks/Vs
        for (int i = tid; i < 64 * 16; i += 128) {
            const int row = i >> 4, c4 = (i & 15) * 4;
            const size_t go = (size_t)(j * 64 + row) * 3072 + c4;
            const float4 kv = *(const float4*)(kb + go);
            const float4 vv = *(const float4*)(vb + go);
            uint32_t* dk = &Ks[row * SP + c4];
            dk[0] = f2tf32(kv.x); dk[1] = f2tf32(kv.y);
            dk[2] = f2tf32(kv.z); dk[3] = f2tf32(kv.w);
            uint32_t* dv = &Vs[row * SP + c4];
            dv[0] = f2tf32(vv.x); dv[1] = f2tf32(vv.y);
            dv[2] = f2tf32(vv.z); dv[3] = f2tf32(vv.w);
        }
        __syncthreads();

        // S[16 x 64] = Q @ K^T   (K is B-operand, col-major: n = kv row, k = d)
        float s[8][4];
        #pragma unroll
        for (int nt = 0; nt < 8; ++nt) {
            s[nt][0] = s[nt][1] = s[nt][2] = s[nt][3] = 0.f;
            const int kr = (nt * 8 + g) * SP;
            #pragma unroll
            for (int ks = 0; ks < 8; ++ks)
                mma8(s[nt], qa[ks], Ks[kr + ks * 8 + tg], Ks[kr + ks * 8 + tg + 4]);
        }

        // Online softmax (rows g and g+8; quad-shuffle reductions)
        float tm0 = -1e30f, tm1 = -1e30f;
        #pragma unroll
        for (int nt = 0; nt < 8; ++nt) {
            tm0 = fmaxf(tm0, fmaxf(s[nt][0], s[nt][1]));
            tm1 = fmaxf(tm1, fmaxf(s[nt][2], s[nt][3]));
        }
        tm0 = fmaxf(tm0, __shfl_xor_sync(0xffffffffu, tm0, 1));
        tm0 = fmaxf(tm0, __shfl_xor_sync(0xffffffffu, tm0, 2));
        tm1 = fmaxf(tm1, __shfl_xor_sync(0xffffffffu, tm1, 1));
        tm1 = fmaxf(tm1, __shfl_xor_sync(0xffffffffu, tm1, 2));
        const float mn0 = fmaxf(m0, tm0), mn1 = fmaxf(m1, tm1);
        const float al0 = __expf(m0 - mn0), al1 = __expf(m1 - mn1);
        float rs0 = 0.f, rs1 = 0.f;
        #pragma unroll
        for (int nt = 0; nt < 8; ++nt) {
            s[nt][0] = __expf(s[nt][0] - mn0);
            s[nt][1] = __expf(s[nt][1] - mn0);
            s[nt][2] = __expf(s[nt][2] - mn1);
            s[nt][3] = __expf(s[nt][3] - mn1);
            rs0 += s[nt][0] + s[nt][1];
            rs1 += s[nt][2] + s[nt][3];
        }
        rs0 += __shfl_xor_sync(0xffffffffu, rs0, 1);
        rs0 += __shfl_xor_sync(0xffffffffu, rs0, 2);
        rs1 += __shfl_xor_sync(0xffffffffu, rs1, 1);
        rs1 += __shfl_xor_sync(0xffffffffu, rs1, 2);
        l0 = l0 * al0 + rs0;
        l1 = l1 * al1 + rs1;
        m0 = mn0; m1 = mn1;
        #pragma unroll
        for (int nt = 0; nt < 8; ++nt) {
            o[nt][0] *= al0; o[nt][1] *= al0;
            o[nt][2] *= al1; o[nt][3] *= al1;
        }

        // Re-fragment P: C-layout -> shared (warp-private rows) -> A-layout
        const int pr0 = (w * 16 + g) * SP, pr1 = pr0 + 8 * SP;
        #pragma unroll
        for (int nt = 0; nt < 8; ++nt) {
            const int c = nt * 8 + tg * 2;
            QP[pr0 + c]     = f2tf32(s[nt][0]);
            QP[pr0 + c + 1] = f2tf32(s[nt][1]);
            QP[pr1 + c]     = f2tf32(s[nt][2]);
            QP[pr1 + c + 1] = f2tf32(s[nt][3]);
        }
        __syncwarp();

        // O += P @ V  (V is B-operand, col-major: k = kv row, n = d)
        #pragma unroll
        for (int kt = 0; kt < 8; ++kt) {
            uint32_t pa[4];
            pa[0] = QP[pr0 + kt * 8 + tg];
            pa[1] = QP[pr1 + kt * 8 + tg];
            pa[2] = QP[pr0 + kt * 8 + tg + 4];
            pa[3] = QP[pr1 + kt * 8 + tg + 4];
            const int vr0 = (kt * 8 + tg) * SP;
            const int vr1 = (kt * 8 + tg + 4) * SP;
            #pragma unroll
            for (int nt = 0; nt < 8; ++nt)
                mma8(o[nt], pa, Vs[vr0 + nt * 8 + g], Vs[vr1 + nt * 8 + g]);
        }
    }

    // Epilogue: normalize and write [b, n, h*64 + d]
    const float il0 = 1.f / l0, il1 = 1.f / l1;
    const int r0 = qb * 64 + w * 16 + g;
    float* ob = g_attn + ((size_t)b * 2048 + r0) * 1024 + h * 64;
    (void)out;
    #pragma unroll
    for (int nt = 0; nt < 8; ++nt) {
        const int c = nt * 8 + tg * 2;
        *(float2*)(ob + c) = make_float2(o[nt][0] * il0, o[nt][1] * il0);
        *(float2*)(ob + (size_t)8 * 1024 + c) = make_float2(o[nt][2] * il1, o[nt][3] * il1);
    }
}

// ---------------------------------------------------------------------------
// Launch
// ---------------------------------------------------------------------------
extern "C" void kernel_launch(void* const* d_in, const int* in_sizes, int n_in,
                              void* d_out, int out_size)
{
    const float *x = nullptr, *wqkv = nullptr, *wproj = nullptr, *bias = nullptr;
    for (int i = 0; i < n_in; ++i) {
        switch (in_sizes[i]) {
            case 4 * 2048 * 1024: x     = (const float*)d_in[i]; break;  // 8388608
            case 3 * 1024 * 1024: wqkv  = (const float*)d_in[i]; break;  // 3145728
            case 1024 * 1024:     wproj = (const float*)d_in[i]; break;  // 1048576
            case 1024:            bias  = (const float*)d_in[i]; break;
        }
    }
    if (!x || !wqkv || !wproj || !bias) {  // positional fallback
        x = (const float*)d_in[0];
        wqkv = (const float*)d_in[1];
        wproj = (const float*)d_in[2];
        bias = (const float*)d_in[3];
    }

    float *qkv_buf, *attn_buf;
    cudaGetSymbolAddress((void**)&qkv_buf, g_qkv);
    cudaGetSymbolAddress((void**)&attn_buf, g_attn);
    float* out = (float*)d_out;

    constexpr int M = 4 * 2048;  // 8192 tokens

    // 1) qkv = x @ W_qkv^T   [8192, 3072]
    gemm_kernel<false><<<dim3(3072 / BN, M / BM), 256>>>(
        x, wqkv, nullptr, qkv_buf, M, 3072, 1024);

    // 2) flash attention -> g_attn [8192, 1024]
    const int smem = 3 * 64 * SP * 4;  // 52224 bytes
    cudaFuncSetAttribute(attn_kernel, cudaFuncAttributeMaxDynamicSharedMemorySize, smem);
    attn_kernel<<<dim3(32, 64), 128, smem>>>(qkv_buf, attn_buf);

    // 3) out = attn @ W_proj^T + b
    gemm_kernel<true><<<dim3(1024 / BN, M / BM), 256>>>(
        attn_buf, wproj, bias, out, M, 1024, 1024);
    (void)out_size;
}

// round 13
// speedup vs baseline: 1.1050x; 1.1035x over previous
#include <cuda_runtime.h>
#include <stdint.h>

#define DEV_INLINE __device__ __forceinline__

// ---------------------------------------------------------------------------
// Helpers
// ---------------------------------------------------------------------------
DEV_INLINE uint32_t f2tf32(float f) {
    uint32_t u;
    asm("cvt.rna.tf32.f32 %0, %1;" : "=r"(u) : "f"(f));
    return u;
}

// D = A(16x8, tf32, row) * B(8x8, tf32, col) + D, fp32 accumulate
DEV_INLINE void mma8(float* c, const uint32_t* a, uint32_t b0, uint32_t b1) {
    asm volatile(
        "mma.sync.aligned.m16n8k8.row.col.f32.tf32.tf32.f32 "
        "{%0,%1,%2,%3}, {%4,%5,%6,%7}, {%8,%9}, {%0,%1,%2,%3};\n"
        : "+f"(c[0]), "+f"(c[1]), "+f"(c[2]), "+f"(c[3])
        : "r"(a[0]), "r"(a[1]), "r"(a[2]), "r"(a[3]), "r"(b0), "r"(b1));
}

DEV_INLINE void cp16(uint32_t dst, const void* src) {
    asm volatile("cp.async.cg.shared.global [%0], [%1], 16;\n" :: "r"(dst), "l"(src));
}
DEV_INLINE void cp_commit() { asm volatile("cp.async.commit_group;\n" ::: "memory"); }
template <int N> DEV_INLINE void cp_wait() {
    asm volatile("cp.async.wait_group %0;\n" :: "n"(N) : "memory");
}

// ---------------------------------------------------------------------------
// Scratch (no cudaMalloc allowed) — all tf32-bit buffers
// ---------------------------------------------------------------------------
__device__ uint32_t g_x32[(size_t)4 * 2048 * 1024];     // x as tf32 bits
__device__ uint32_t g_wqkv32[(size_t)3 * 1024 * 1024];  // W_qkv as tf32 bits
__device__ uint32_t g_wproj32[(size_t)1024 * 1024];     // W_proj as tf32 bits
__device__ uint32_t g_qkv[(size_t)4 * 2048 * 3072];     // qkv as tf32 bits (Q pre-scaled)
__device__ uint32_t g_attn[(size_t)4 * 2048 * 1024];    // attn out as tf32 bits

// ---------------------------------------------------------------------------
// fp32 -> tf32-bits elementwise conversion
// ---------------------------------------------------------------------------
__global__ void cvt_kernel(const float4* __restrict__ in, uint4* __restrict__ out, int n4) {
    int i = blockIdx.x * blockDim.x + threadIdx.x;
    const int stride = gridDim.x * blockDim.x;
    for (; i < n4; i += stride) {
        const float4 v = in[i];
        out[i] = make_uint4(f2tf32(v.x), f2tf32(v.y), f2tf32(v.z), f2tf32(v.w));
    }
}

// ---------------------------------------------------------------------------
// GEMM: C[M,N] = A[M,K] @ B[N,K]^T, tf32 bits in, no cvt in hot loop.
// CTA tile 128x128, K-tile 16, 8 warps (2x4), warp tile 64x32.
// OUTMODE 0: write tf32 bits, cols<1024 scaled 0.125 (qkv producer)
// OUTMODE 1: write fp32 + bias (final projection)
// ---------------------------------------------------------------------------
constexpr int BM = 128, BN = 128, BK = 16;
constexpr int GP = 20;  // shared pitch (u32): conflict-free quad fragment loads

template <int OUTMODE>
__global__ void __launch_bounds__(256) gemm_kernel(
    const uint32_t* __restrict__ A, const uint32_t* __restrict__ B,
    const float* __restrict__ bias, void* __restrict__ Cv,
    int M, int N, int K)
{
    __shared__ uint32_t As[2][BM * GP];
    __shared__ uint32_t Bs[2][BN * GP];

    const int bm = blockIdx.y * BM;
    const int bn = blockIdx.x * BN;
    const int tid = threadIdx.x;
    const int lane = tid & 31;
    const int wid = tid >> 5;
    const int g = lane >> 2, tg = lane & 3;
    const int wm = (wid >> 2) * 64;
    const int wn = (wid & 3) * 32;

    const int lrow = tid >> 2;
    const int lcol = (tid & 3) * 4;

    const uint32_t* Ag = A + (size_t)(bm + lrow) * K + lcol;
    const uint32_t* Bg = B + (size_t)(bn + lrow) * K + lcol;
    const uint32_t sA = (uint32_t)__cvta_generic_to_shared(&As[0][lrow * GP + lcol]);
    const uint32_t sB = (uint32_t)__cvta_generic_to_shared(&Bs[0][lrow * GP + lcol]);
    const uint32_t bufBytes = BM * GP * 4;
    const uint32_t rowHop = 64 * GP * 4;

    float acc[4][4][4];
    #pragma unroll
    for (int mt = 0; mt < 4; ++mt)
        #pragma unroll
        for (int nt = 0; nt < 4; ++nt)
            #pragma unroll
            for (int v = 0; v < 4; ++v)
                acc[mt][nt][v] = 0.f;

    const int KT = K / BK;

    cp16(sA, Ag);
    cp16(sA + rowHop, Ag + (size_t)64 * K);
    cp16(sB, Bg);
    cp16(sB + rowHop, Bg + (size_t)64 * K);
    cp_commit();

    for (int kt = 0; kt < KT; ++kt) {
        if (kt + 1 < KT) {
            const uint32_t* a = Ag + (size_t)(kt + 1) * BK;
            const uint32_t* b = Bg + (size_t)(kt + 1) * BK;
            const uint32_t off = ((kt + 1) & 1) ? bufBytes : 0u;
            cp16(sA + off, a);
            cp16(sA + off + rowHop, a + (size_t)64 * K);
            cp16(sB + off, b);
            cp16(sB + off + rowHop, b + (size_t)64 * K);
            cp_commit();
            cp_wait<1>();
        } else {
            cp_wait<0>();
        }
        __syncthreads();

        const uint32_t* as = As[kt & 1];
        const uint32_t* bs = Bs[kt & 1];
        #pragma unroll
        for (int ks = 0; ks < 2; ++ks) {
            const int ko = ks * 8;
            uint32_t af[4][4];
            #pragma unroll
            for (int mt = 0; mt < 4; ++mt) {
                const int r = wm + mt * 16 + g;
                af[mt][0] = as[r * GP + ko + tg];
                af[mt][1] = as[(r + 8) * GP + ko + tg];
                af[mt][2] = as[r * GP + ko + tg + 4];
                af[mt][3] = as[(r + 8) * GP + ko + tg + 4];
            }
            uint32_t bf[4][2];
            #pragma unroll
            for (int nt = 0; nt < 4; ++nt) {
                const int r = wn + nt * 8 + g;
                bf[nt][0] = bs[r * GP + ko + tg];
                bf[nt][1] = bs[r * GP + ko + tg + 4];
            }
            #pragma unroll
            for (int mt = 0; mt < 4; ++mt)
                #pragma unroll
                for (int nt = 0; nt < 4; ++nt)
                    mma8(acc[mt][nt], af[mt], bf[nt][0], bf[nt][1]);
        }
        __syncthreads();
    }

    // epilogue
    #pragma unroll
    for (int mt = 0; mt < 4; ++mt) {
        const int row = bm + wm + mt * 16 + g;
        #pragma unroll
        for (int nt = 0; nt < 4; ++nt) {
            const int col = bn + wn + nt * 8 + tg * 2;
            if (OUTMODE == 1) {
                float* C = (float*)Cv;
                const float2 bb = *(const float2*)(bias + col);
                float2 v0 = make_float2(acc[mt][nt][0] + bb.x, acc[mt][nt][1] + bb.y);
                float2 v1 = make_float2(acc[mt][nt][2] + bb.x, acc[mt][nt][3] + bb.y);
                *(float2*)(C + (size_t)row * N + col) = v0;
                *(float2*)(C + (size_t)(row + 8) * N + col) = v1;
            } else {
                uint32_t* C = (uint32_t*)Cv;
                const float sc = (col < 1024) ? 0.125f : 1.0f;  // Q pre-scale
                uint2 v0 = make_uint2(f2tf32(acc[mt][nt][0] * sc), f2tf32(acc[mt][nt][1] * sc));
                uint2 v1 = make_uint2(f2tf32(acc[mt][nt][2] * sc), f2tf32(acc[mt][nt][3] * sc));
                *(uint2*)(C + (size_t)row * N + col) = v0;
                *(uint2*)(C + (size_t)(row + 8) * N + col) = v1;
            }
        }
    }
}

// ---------------------------------------------------------------------------
// Flash attention: grid (16 q-blocks, 64 b*h), 256 threads (8 warps x 16 rows)
// BLOCK_M = 128, BLOCK_N = 64, D = 64. tf32 bits in smem, cp.async double-buffer.
// ---------------------------------------------------------------------------
constexpr int KP = 68;  // pitch for Q/P/K (conflict-free A/S-frag loads)
constexpr int VP = 72;  // pitch for V (conflict-free PV B-frag loads)

// smem layout (u32 indices)
constexpr int OFF_K0 = 128 * KP;            // 8704
constexpr int OFF_K1 = OFF_K0 + 64 * KP;    // 13056
constexpr int OFF_V0 = OFF_K1 + 64 * KP;    // 17408
constexpr int OFF_V1 = OFF_V0 + 64 * VP;    // 22016
constexpr int SMEM_U32 = OFF_V1 + 64 * VP;  // 26624 -> 106496 bytes

__global__ void __launch_bounds__(256) attn_kernel(
    const uint32_t* __restrict__ qkv, uint32_t* __restrict__ outb)
{
    extern __shared__ uint32_t sh[];
    uint32_t* QP = sh;  // Q staging, then P staging (warp-private rows)

    const int bh = blockIdx.y;
    const int b = bh >> 4, h = bh & 15;
    const int qb = blockIdx.x;
    const int tid = threadIdx.x, w = tid >> 5, lane = tid & 31;
    const int g = lane >> 2, tg = lane & 3;

    const uint32_t* base = qkv + (size_t)b * 2048 * 3072 + h * 64;
    const uint32_t* kb = base + 1024;
    const uint32_t* vb = base + 2048;

    const uint32_t shb = (uint32_t)__cvta_generic_to_shared(sh);

    // Q tile [128][64] (tf32 bits, pre-scaled) via cp.async — group 0
    for (int i = tid; i < 2048; i += 256) {
        const int row = i >> 4, c4 = (i & 15) * 4;
        cp16(shb + (uint32_t)(row * KP + c4) * 4,
             base + (size_t)(qb * 128 + row) * 3072 + c4);
    }
    cp_commit();

    // K/V tile 0 — group 1
    for (int i = tid; i < 1024; i += 256) {
        const int row = i >> 4, c4 = (i & 15) * 4;
        cp16(shb + (uint32_t)(OFF_K0 + row * KP + c4) * 4, kb + (size_t)row * 3072 + c4);
        cp16(shb + (uint32_t)(OFF_V0 + row * VP + c4) * 4, vb + (size_t)row * 3072 + c4);
    }
    cp_commit();

    cp_wait<1>();        // Q ready (tile 0 may still be in flight)
    __syncthreads();

    // Q A-fragments in registers: 8 k-tiles over D=64
    uint32_t qa[8][4];
    {
        const int r0 = (w * 16 + g) * KP, r1 = r0 + 8 * KP;
        #pragma unroll
        for (int ks = 0; ks < 8; ++ks) {
            qa[ks][0] = QP[r0 + ks * 8 + tg];
            qa[ks][1] = QP[r1 + ks * 8 + tg];
            qa[ks][2] = QP[r0 + ks * 8 + tg + 4];
            qa[ks][3] = QP[r1 + ks * 8 + tg + 4];
        }
    }

    float m0 = -1e30f, m1 = -1e30f, l0 = 0.f, l1 = 0.f;
    float o[8][4];
    #pragma unroll
    for (int nt = 0; nt < 8; ++nt)
        o[nt][0] = o[nt][1] = o[nt][2] = o[nt][3] = 0.f;

    for (int j = 0; j < 32; ++j) {
        // prefetch tile j+1 into the other buffer, then wait for tile j
        if (j + 1 < 32) {
            const int buf = (j + 1) & 1;
            const uint32_t kd = shb + (uint32_t)(buf ? OFF_K1 : OFF_K0) * 4;
            const uint32_t vd = shb + (uint32_t)(buf ? OFF_V1 : OFF_V0) * 4;
            const uint32_t* kg = kb + (size_t)(j + 1) * 64 * 3072;
            const uint32_t* vg = vb + (size_t)(j + 1) * 64 * 3072;
            for (int i = tid; i < 1024; i += 256) {
                const int row = i >> 4, c4 = (i & 15) * 4;
                cp16(kd + (uint32_t)(row * KP + c4) * 4, kg + (size_t)row * 3072 + c4);
                cp16(vd + (uint32_t)(row * VP + c4) * 4, vg + (size_t)row * 3072 + c4);
            }
            cp_commit();
            cp_wait<1>();
        } else {
            cp_wait<0>();
        }
        __syncthreads();

        const uint32_t* Kc = sh + ((j & 1) ? OFF_K1 : OFF_K0);
        const uint32_t* Vc = sh + ((j & 1) ? OFF_V1 : OFF_V0);

        // S[16 x 64] = Q @ K^T
        float s[8][4];
        #pragma unroll
        for (int nt = 0; nt < 8; ++nt) {
            s[nt][0] = s[nt][1] = s[nt][2] = s[nt][3] = 0.f;
            const int kr = (nt * 8 + g) * KP;
            #pragma unroll
            for (int ks = 0; ks < 8; ++ks)
                mma8(s[nt], qa[ks], Kc[kr + ks * 8 + tg], Kc[kr + ks * 8 + tg + 4]);
        }

        // Online softmax (rows g and g+8; quad-shuffle reductions)
        float tm0 = -1e30f, tm1 = -1e30f;
        #pragma unroll
        for (int nt = 0; nt < 8; ++nt) {
            tm0 = fmaxf(tm0, fmaxf(s[nt][0], s[nt][1]));
            tm1 = fmaxf(tm1, fmaxf(s[nt][2], s[nt][3]));
        }
        tm0 = fmaxf(tm0, __shfl_xor_sync(0xffffffffu, tm0, 1));
        tm0 = fmaxf(tm0, __shfl_xor_sync(0xffffffffu, tm0, 2));
        tm1 = fmaxf(tm1, __shfl_xor_sync(0xffffffffu, tm1, 1));
        tm1 = fmaxf(tm1, __shfl_xor_sync(0xffffffffu, tm1, 2));
        const float mn0 = fmaxf(m0, tm0), mn1 = fmaxf(m1, tm1);
        const float al0 = __expf(m0 - mn0), al1 = __expf(m1 - mn1);
        float rs0 = 0.f, rs1 = 0.f;
        #pragma unroll
        for (int nt = 0; nt < 8; ++nt) {
            s[nt][0] = __expf(s[nt][0] - mn0);
            s[nt][1] = __expf(s[nt][1] - mn0);
            s[nt][2] = __expf(s[nt][2] - mn1);
            s[nt][3] = __expf(s[nt][3] - mn1);
            rs0 += s[nt][0] + s[nt][1];
            rs1 += s[nt][2] + s[nt][3];
        }
        rs0 += __shfl_xor_sync(0xffffffffu, rs0, 1);
        rs0 += __shfl_xor_sync(0xffffffffu, rs0, 2);
        rs1 += __shfl_xor_sync(0xffffffffu, rs1, 1);
        rs1 += __shfl_xor_sync(0xffffffffu, rs1, 2);
        l0 = l0 * al0 + rs0;
        l1 = l1 * al1 + rs1;
        m0 = mn0; m1 = mn1;
        #pragma unroll
        for (int nt = 0; nt < 8; ++nt) {
            o[nt][0] *= al0; o[nt][1] *= al0;
            o[nt][2] *= al1; o[nt][3] *= al1;
        }

        // Re-fragment P: C-layout -> shared (warp-private rows) -> A-layout
        const int pr0 = (w * 16 + g) * KP, pr1 = pr0 + 8 * KP;
        #pragma unroll
        for (int nt = 0; nt < 8; ++nt) {
            const int c = nt * 8 + tg * 2;
            QP[pr0 + c]     = f2tf32(s[nt][0]);
            QP[pr0 + c + 1] = f2tf32(s[nt][1]);
            QP[pr1 + c]     = f2tf32(s[nt][2]);
            QP[pr1 + c + 1] = f2tf32(s[nt][3]);
        }
        __syncwarp();

        // O += P @ V
        #pragma unroll
        for (int kt = 0; kt < 8; ++kt) {
            uint32_t pa[4];
            pa[0] = QP[pr0 + kt * 8 + tg];
            pa[1] = QP[pr1 + kt * 8 + tg];
            pa[2] = QP[pr0 + kt * 8 + tg + 4];
            pa[3] = QP[pr1 + kt * 8 + tg + 4];
            const int vr0 = (kt * 8 + tg) * VP;
            const int vr1 = (kt * 8 + tg + 4) * VP;
            #pragma unroll
            for (int nt = 0; nt < 8; ++nt)
                mma8(o[nt], pa, Vc[vr0 + nt * 8 + g], Vc[vr1 + nt * 8 + g]);
        }
        __syncthreads();  // all warps done with this buffer before next prefetch
    }

    // Epilogue: normalize, convert to tf32 bits, write [b, n, h*64 + d]
    const float il0 = 1.f / l0, il1 = 1.f / l1;
    const int r0 = qb * 128 + w * 16 + g;
    uint32_t* ob = outb + ((size_t)b * 2048 + r0) * 1024 + h * 64;
    #pragma unroll
    for (int nt = 0; nt < 8; ++nt) {
        const int c = nt * 8 + tg * 2;
        *(uint2*)(ob + c) =
            make_uint2(f2tf32(o[nt][0] * il0), f2tf32(o[nt][1] * il0));
        *(uint2*)(ob + (size_t)8 * 1024 + c) =
            make_uint2(f2tf32(o[nt][2] * il1), f2tf32(o[nt][3] * il1));
    }
}

// ---------------------------------------------------------------------------
// Launch
// ---------------------------------------------------------------------------
extern "C" void kernel_launch(void* const* d_in, const int* in_sizes, int n_in,
                              void* d_out, int out_size)
{
    const float *x = nullptr, *wqkv = nullptr, *wproj = nullptr, *bias = nullptr;
    for (int i = 0; i < n_in; ++i) {
        switch (in_sizes[i]) {
            case 4 * 2048 * 1024: x     = (const float*)d_in[i]; break;
            case 3 * 1024 * 1024: wqkv  = (const float*)d_in[i]; break;
            case 1024 * 1024:     wproj = (const float*)d_in[i]; break;
            case 1024:            bias  = (const float*)d_in[i]; break;
        }
    }
    if (!x || !wqkv || !wproj || !bias) {
        x = (const float*)d_in[0];
        wqkv = (const float*)d_in[1];
        wproj = (const float*)d_in[2];
        bias = (const float*)d_in[3];
    }

    uint32_t *x32, *wqkv32, *wproj32, *qkv_buf, *attn_buf;
    cudaGetSymbolAddress((void**)&x32, g_x32);
    cudaGetSymbolAddress((void**)&wqkv32, g_wqkv32);
    cudaGetSymbolAddress((void**)&wproj32, g_wproj32);
    cudaGetSymbolAddress((void**)&qkv_buf, g_qkv);
    cudaGetSymbolAddress((void**)&attn_buf, g_attn);
    float* out = (float*)d_out;

    constexpr int M = 4 * 2048;  // 8192 tokens

    // 0) one-time tf32 conversion of all GEMM inputs
    cvt_kernel<<<1184, 256>>>((const float4*)x, (uint4*)x32, (4 * 2048 * 1024) / 4);
    cvt_kernel<<<592, 256>>>((const float4*)wqkv, (uint4*)wqkv32, (3 * 1024 * 1024) / 4);
    cvt_kernel<<<296, 256>>>((const float4*)wproj, (uint4*)wproj32, (1024 * 1024) / 4);

    // 1) qkv = x @ W_qkv^T  [8192, 3072] as tf32 bits, Q pre-scaled 0.125
    gemm_kernel<0><<<dim3(3072 / BN, M / BM), 256>>>(
        x32, wqkv32, nullptr, qkv_buf, M, 3072, 1024);

    // 2) flash attention -> g_attn [8192, 1024] tf32 bits
    const int smem = SMEM_U32 * 4;  // 106496 bytes
    cudaFuncSetAttribute(attn_kernel, cudaFuncAttributeMaxDynamicSharedMemorySize, smem);
    attn_kernel<<<dim3(16, 64), 256, smem>>>(qkv_buf, attn_buf);

    // 3) out = attn @ W_proj^T + b  (fp32)
    gemm_kernel<1><<<dim3(1024 / BN, M / BM), 256>>>(
        attn_buf, wproj32, bias, out, M, 1024, 1024);
    (void)out_size;
}

// round 14
// speedup vs baseline: 1.2048x; 1.0903x over previous
#include <cuda_runtime.h>
#include <stdint.h>

#define DEV_INLINE __device__ __forceinline__

// ---------------------------------------------------------------------------
// Helpers
// ---------------------------------------------------------------------------
DEV_INLINE uint32_t f2tf32(float f) {
    uint32_t u;
    asm("cvt.rna.tf32.f32 %0, %1;" : "=r"(u) : "f"(f));
    return u;
}

// D = A(16x8, tf32, row) * B(8x8, tf32, col) + D, fp32 accumulate
DEV_INLINE void mma8(float* c, const uint32_t* a, uint32_t b0, uint32_t b1) {
    asm volatile(
        "mma.sync.aligned.m16n8k8.row.col.f32.tf32.tf32.f32 "
        "{%0,%1,%2,%3}, {%4,%5,%6,%7}, {%8,%9}, {%0,%1,%2,%3};\n"
        : "+f"(c[0]), "+f"(c[1]), "+f"(c[2]), "+f"(c[3])
        : "r"(a[0]), "r"(a[1]), "r"(a[2]), "r"(a[3]), "r"(b0), "r"(b1));
}

DEV_INLINE void cp16(uint32_t dst, const void* src) {
    asm volatile("cp.async.cg.shared.global [%0], [%1], 16;\n" :: "r"(dst), "l"(src));
}
DEV_INLINE void cp_commit() { asm volatile("cp.async.commit_group;\n" ::: "memory"); }
template <int N> DEV_INLINE void cp_wait() {
    asm volatile("cp.async.wait_group %0;\n" :: "n"(N) : "memory");
}

// ---------------------------------------------------------------------------
// Scratch (no cudaMalloc allowed) — all tf32-bit buffers
// ---------------------------------------------------------------------------
__device__ uint32_t g_x32[(size_t)4 * 2048 * 1024];     // x as tf32 bits
__device__ uint32_t g_wqkv32[(size_t)3 * 1024 * 1024];  // W_qkv as tf32 bits
__device__ uint32_t g_wproj32[(size_t)1024 * 1024];     // W_proj as tf32 bits
__device__ uint32_t g_qkv[(size_t)4 * 2048 * 3072];     // qkv as tf32 bits (Q pre-scaled)
__device__ uint32_t g_attn[(size_t)4 * 2048 * 1024];    // attn out as tf32 bits

// ---------------------------------------------------------------------------
// fp32 -> tf32-bits elementwise conversion
// ---------------------------------------------------------------------------
__global__ void cvt_kernel(const float4* __restrict__ in, uint4* __restrict__ out, int n4) {
    int i = blockIdx.x * blockDim.x + threadIdx.x;
    const int stride = gridDim.x * blockDim.x;
    for (; i < n4; i += stride) {
        const float4 v = in[i];
        out[i] = make_uint4(f2tf32(v.x), f2tf32(v.y), f2tf32(v.z), f2tf32(v.w));
    }
}

// ---------------------------------------------------------------------------
// GEMM: C[M,N] = A[M,K] @ B[N,K]^T, tf32 bits in, no cvt in hot loop.
// CTA tile 128x128, K-slab 32 (4 mma k-steps per barrier), 8 warps (2x4),
// warp tile 64x32, 2-stage cp.async double buffer in dynamic smem.
// OUTMODE 0: write tf32 bits, cols<1024 scaled 0.125 (qkv producer)
// OUTMODE 1: write fp32 + bias (final projection)
// ---------------------------------------------------------------------------
constexpr int BM = 128, BN = 128, BK = 32;
constexpr int GP = 36;                     // pitch (u32), ==4 mod 32: conflict-free frags
constexpr int STAGE_U32 = BM * GP;         // 4608 u32 per matrix per stage
constexpr int GEMM_SMEM = 4 * STAGE_U32 * 4;  // 2 stages x (A+B) = 73728 bytes

template <int OUTMODE>
__global__ void __launch_bounds__(256, 2) gemm_kernel(
    const uint32_t* __restrict__ A, const uint32_t* __restrict__ B,
    const float* __restrict__ bias, void* __restrict__ Cv,
    int M, int N, int K)
{
    extern __shared__ uint32_t smem[];
    // layout: As[0], As[1], Bs[0], Bs[1]
    uint32_t* Asm = smem;
    uint32_t* Bsm = smem + 2 * STAGE_U32;

    const int bm = blockIdx.y * BM;
    const int bn = blockIdx.x * BN;
    const int tid = threadIdx.x;
    const int lane = tid & 31;
    const int wid = tid >> 5;
    const int g = lane >> 2, tg = lane & 3;
    const int wm = (wid >> 2) * 64;
    const int wn = (wid & 3) * 32;

    // cooperative load: 128 rows x 32 u32 = 1024 float4 per matrix per stage;
    // 256 threads -> 4 float4 each. row = i>>3, c4 = (i&7)*4.
    const int lrow = tid >> 3;        // 0..31 base row
    const int lcol = (tid & 7) * 4;   // 0..28

    const uint32_t* Ag = A + (size_t)(bm + lrow) * K + lcol;
    const uint32_t* Bg = B + (size_t)(bn + lrow) * K + lcol;
    const uint32_t sA0 = (uint32_t)__cvta_generic_to_shared(&Asm[lrow * GP + lcol]);
    const uint32_t sB0 = (uint32_t)__cvta_generic_to_shared(&Bsm[lrow * GP + lcol]);
    const uint32_t stageBytes = STAGE_U32 * 4;
    const uint32_t rowHop = 32 * GP * 4;  // 32 rows per cp iteration

    float acc[4][4][4];
    #pragma unroll
    for (int mt = 0; mt < 4; ++mt)
        #pragma unroll
        for (int nt = 0; nt < 4; ++nt)
            #pragma unroll
            for (int v = 0; v < 4; ++v)
                acc[mt][nt][v] = 0.f;

    const int KT = K / BK;  // 32

    // prefetch slab 0 into stage 0
    #pragma unroll
    for (int r = 0; r < 4; ++r) {
        cp16(sA0 + r * rowHop, Ag + (size_t)(r * 32) * K);
        cp16(sB0 + r * rowHop, Bg + (size_t)(r * 32) * K);
    }
    cp_commit();

    for (int kt = 0; kt < KT; ++kt) {
        if (kt + 1 < KT) {
            const uint32_t* a = Ag + (size_t)(kt + 1) * BK;
            const uint32_t* b = Bg + (size_t)(kt + 1) * BK;
            const uint32_t off = ((kt + 1) & 1) ? stageBytes : 0u;
            #pragma unroll
            for (int r = 0; r < 4; ++r) {
                cp16(sA0 + off + r * rowHop, a + (size_t)(r * 32) * K);
                cp16(sB0 + off + r * rowHop, b + (size_t)(r * 32) * K);
            }
            cp_commit();
            cp_wait<1>();
        } else {
            cp_wait<0>();
        }
        __syncthreads();

        const uint32_t* as = Asm + (kt & 1) * STAGE_U32;
        const uint32_t* bs = Bsm + (kt & 1) * STAGE_U32;
        #pragma unroll
        for (int ks = 0; ks < 4; ++ks) {
            const int ko = ks * 8;
            uint32_t af[4][4];
            #pragma unroll
            for (int mt = 0; mt < 4; ++mt) {
                const int r = wm + mt * 16 + g;
                af[mt][0] = as[r * GP + ko + tg];
                af[mt][1] = as[(r + 8) * GP + ko + tg];
                af[mt][2] = as[r * GP + ko + tg + 4];
                af[mt][3] = as[(r + 8) * GP + ko + tg + 4];
            }
            uint32_t bf[4][2];
            #pragma unroll
            for (int nt = 0; nt < 4; ++nt) {
                const int r = wn + nt * 8 + g;
                bf[nt][0] = bs[r * GP + ko + tg];
                bf[nt][1] = bs[r * GP + ko + tg + 4];
            }
            #pragma unroll
            for (int mt = 0; mt < 4; ++mt)
                #pragma unroll
                for (int nt = 0; nt < 4; ++nt)
                    mma8(acc[mt][nt], af[mt], bf[nt][0], bf[nt][1]);
        }
        __syncthreads();
    }

    // epilogue
    #pragma unroll
    for (int mt = 0; mt < 4; ++mt) {
        const int row = bm + wm + mt * 16 + g;
        #pragma unroll
        for (int nt = 0; nt < 4; ++nt) {
            const int col = bn + wn + nt * 8 + tg * 2;
            if (OUTMODE == 1) {
                float* C = (float*)Cv;
                const float2 bb = *(const float2*)(bias + col);
                float2 v0 = make_float2(acc[mt][nt][0] + bb.x, acc[mt][nt][1] + bb.y);
                float2 v1 = make_float2(acc[mt][nt][2] + bb.x, acc[mt][nt][3] + bb.y);
                *(float2*)(C + (size_t)row * N + col) = v0;
                *(float2*)(C + (size_t)(row + 8) * N + col) = v1;
            } else {
                uint32_t* C = (uint32_t*)Cv;
                const float sc = (col < 1024) ? 0.125f : 1.0f;  // Q pre-scale
                uint2 v0 = make_uint2(f2tf32(acc[mt][nt][0] * sc), f2tf32(acc[mt][nt][1] * sc));
                uint2 v1 = make_uint2(f2tf32(acc[mt][nt][2] * sc), f2tf32(acc[mt][nt][3] * sc));
                *(uint2*)(C + (size_t)row * N + col) = v0;
                *(uint2*)(C + (size_t)(row + 8) * N + col) = v1;
            }
        }
    }
}

// ---------------------------------------------------------------------------
// Flash attention: grid (16 q-blocks, 64 b*h), 256 threads (8 warps x 16 rows)
// BLOCK_M = 128, BLOCK_N = 64, D = 64. tf32 bits in smem, cp.async double-buffer.
// ---------------------------------------------------------------------------
constexpr int KP = 68;  // pitch for Q/P/K (conflict-free A/S-frag loads)
constexpr int VP = 72;  // pitch for V (conflict-free PV B-frag loads)

// smem layout (u32 indices)
constexpr int OFF_K0 = 128 * KP;            // 8704
constexpr int OFF_K1 = OFF_K0 + 64 * KP;    // 13056
constexpr int OFF_V0 = OFF_K1 + 64 * KP;    // 17408
constexpr int OFF_V1 = OFF_V0 + 64 * VP;    // 22016
constexpr int SMEM_U32 = OFF_V1 + 64 * VP;  // 26624 -> 106496 bytes

__global__ void __launch_bounds__(256) attn_kernel(
    const uint32_t* __restrict__ qkv, uint32_t* __restrict__ outb)
{
    extern __shared__ uint32_t sh[];
    uint32_t* QP = sh;  // Q staging, then P staging (warp-private rows)

    const int bh = blockIdx.y;
    const int b = bh >> 4, h = bh & 15;
    const int qb = blockIdx.x;
    const int tid = threadIdx.x, w = tid >> 5, lane = tid & 31;
    const int g = lane >> 2, tg = lane & 3;

    const uint32_t* base = qkv + (size_t)b * 2048 * 3072 + h * 64;
    const uint32_t* kb = base + 1024;
    const uint32_t* vb = base + 2048;

    const uint32_t shb = (uint32_t)__cvta_generic_to_shared(sh);

    // Q tile [128][64] (tf32 bits, pre-scaled) via cp.async — group 0
    for (int i = tid; i < 2048; i += 256) {
        const int row = i >> 4, c4 = (i & 15) * 4;
        cp16(shb + (uint32_t)(row * KP + c4) * 4,
             base + (size_t)(qb * 128 + row) * 3072 + c4);
    }
    cp_commit();

    // K/V tile 0 — group 1
    for (int i = tid; i < 1024; i += 256) {
        const int row = i >> 4, c4 = (i & 15) * 4;
        cp16(shb + (uint32_t)(OFF_K0 + row * KP + c4) * 4, kb + (size_t)row * 3072 + c4);
        cp16(shb + (uint32_t)(OFF_V0 + row * VP + c4) * 4, vb + (size_t)row * 3072 + c4);
    }
    cp_commit();

    cp_wait<1>();        // Q ready (tile 0 may still be in flight)
    __syncthreads();

    // Q A-fragments in registers: 8 k-tiles over D=64
    uint32_t qa[8][4];
    {
        const int r0 = (w * 16 + g) * KP, r1 = r0 + 8 * KP;
        #pragma unroll
        for (int ks = 0; ks < 8; ++ks) {
            qa[ks][0] = QP[r0 + ks * 8 + tg];
            qa[ks][1] = QP[r1 + ks * 8 + tg];
            qa[ks][2] = QP[r0 + ks * 8 + tg + 4];
            qa[ks][3] = QP[r1 + ks * 8 + tg + 4];
        }
    }

    float m0 = -1e30f, m1 = -1e30f, l0 = 0.f, l1 = 0.f;
    float o[8][4];
    #pragma unroll
    for (int nt = 0; nt < 8; ++nt)
        o[nt][0] = o[nt][1] = o[nt][2] = o[nt][3] = 0.f;

    for (int j = 0; j < 32; ++j) {
        // prefetch tile j+1 into the other buffer, then wait for tile j
        if (j + 1 < 32) {
            const int buf = (j + 1) & 1;
            const uint32_t kd = shb + (uint32_t)(buf ? OFF_K1 : OFF_K0) * 4;
            const uint32_t vd = shb + (uint32_t)(buf ? OFF_V1 : OFF_V0) * 4;
            const uint32_t* kg = kb + (size_t)(j + 1) * 64 * 3072;
            const uint32_t* vg = vb + (size_t)(j + 1) * 64 * 3072;
            for (int i = tid; i < 1024; i += 256) {
                const int row = i >> 4, c4 = (i & 15) * 4;
                cp16(kd + (uint32_t)(row * KP + c4) * 4, kg + (size_t)row * 3072 + c4);
                cp16(vd + (uint32_t)(row * VP + c4) * 4, vg + (size_t)row * 3072 + c4);
            }
            cp_commit();
            cp_wait<1>();
        } else {
            cp_wait<0>();
        }
        __syncthreads();

        const uint32_t* Kc = sh + ((j & 1) ? OFF_K1 : OFF_K0);
        const uint32_t* Vc = sh + ((j & 1) ? OFF_V1 : OFF_V0);

        // S[16 x 64] = Q @ K^T
        float s[8][4];
        #pragma unroll
        for (int nt = 0; nt < 8; ++nt) {
            s[nt][0] = s[nt][1] = s[nt][2] = s[nt][3] = 0.f;
            const int kr = (nt * 8 + g) * KP;
            #pragma unroll
            for (int ks = 0; ks < 8; ++ks)
                mma8(s[nt], qa[ks], Kc[kr + ks * 8 + tg], Kc[kr + ks * 8 + tg + 4]);
        }

        // Online softmax (rows g and g+8; quad-shuffle reductions)
        float tm0 = -1e30f, tm1 = -1e30f;
        #pragma unroll
        for (int nt = 0; nt < 8; ++nt) {
            tm0 = fmaxf(tm0, fmaxf(s[nt][0], s[nt][1]));
            tm1 = fmaxf(tm1, fmaxf(s[nt][2], s[nt][3]));
        }
        tm0 = fmaxf(tm0, __shfl_xor_sync(0xffffffffu, tm0, 1));
        tm0 = fmaxf(tm0, __shfl_xor_sync(0xffffffffu, tm0, 2));
        tm1 = fmaxf(tm1, __shfl_xor_sync(0xffffffffu, tm1, 1));
        tm1 = fmaxf(tm1, __shfl_xor_sync(0xffffffffu, tm1, 2));
        const float mn0 = fmaxf(m0, tm0), mn1 = fmaxf(m1, tm1);
        const float al0 = __expf(m0 - mn0), al1 = __expf(m1 - mn1);
        float rs0 = 0.f, rs1 = 0.f;
        #pragma unroll
        for (int nt = 0; nt < 8; ++nt) {
            s[nt][0] = __expf(s[nt][0] - mn0);
            s[nt][1] = __expf(s[nt][1] - mn0);
            s[nt][2] = __expf(s[nt][2] - mn1);
            s[nt][3] = __expf(s[nt][3] - mn1);
            rs0 += s[nt][0] + s[nt][1];
            rs1 += s[nt][2] + s[nt][3];
        }
        rs0 += __shfl_xor_sync(0xffffffffu, rs0, 1);
        rs0 += __shfl_xor_sync(0xffffffffu, rs0, 2);
        rs1 += __shfl_xor_sync(0xffffffffu, rs1, 1);
        rs1 += __shfl_xor_sync(0xffffffffu, rs1, 2);
        l0 = l0 * al0 + rs0;
        l1 = l1 * al1 + rs1;
        m0 = mn0; m1 = mn1;
        #pragma unroll
        for (int nt = 0; nt < 8; ++nt) {
            o[nt][0] *= al0; o[nt][1] *= al0;
            o[nt][2] *= al1; o[nt][3] *= al1;
        }

        // Re-fragment P: C-layout -> shared (warp-private rows) -> A-layout
        const int pr0 = (w * 16 + g) * KP, pr1 = pr0 + 8 * KP;
        #pragma unroll
        for (int nt = 0; nt < 8; ++nt) {
            const int c = nt * 8 + tg * 2;
            QP[pr0 + c]     = f2tf32(s[nt][0]);
            QP[pr0 + c + 1] = f2tf32(s[nt][1]);
            QP[pr1 + c]     = f2tf32(s[nt][2]);
            QP[pr1 + c + 1] = f2tf32(s[nt][3]);
        }
        __syncwarp();

        // O += P @ V
        #pragma unroll
        for (int kt = 0; kt < 8; ++kt) {
            uint32_t pa[4];
            pa[0] = QP[pr0 + kt * 8 + tg];
            pa[1] = QP[pr1 + kt * 8 + tg];
            pa[2] = QP[pr0 + kt * 8 + tg + 4];
            pa[3] = QP[pr1 + kt * 8 + tg + 4];
            const int vr0 = (kt * 8 + tg) * VP;
            const int vr1 = (kt * 8 + tg + 4) * VP;
            #pragma unroll
            for (int nt = 0; nt < 8; ++nt)
                mma8(o[nt], pa, Vc[vr0 + nt * 8 + g], Vc[vr1 + nt * 8 + g]);
        }
        __syncthreads();  // all warps done with this buffer before next prefetch
    }

    // Epilogue: normalize, convert to tf32 bits, write [b, n, h*64 + d]
    const float il0 = 1.f / l0, il1 = 1.f / l1;
    const int r0 = qb * 128 + w * 16 + g;
    uint32_t* ob = outb + ((size_t)b * 2048 + r0) * 1024 + h * 64;
    #pragma unroll
    for (int nt = 0; nt < 8; ++nt) {
        const int c = nt * 8 + tg * 2;
        *(uint2*)(ob + c) =
            make_uint2(f2tf32(o[nt][0] * il0), f2tf32(o[nt][1] * il0));
        *(uint2*)(ob + (size_t)8 * 1024 + c) =
            make_uint2(f2tf32(o[nt][2] * il1), f2tf32(o[nt][3] * il1));
    }
}

// ---------------------------------------------------------------------------
// Launch
// ---------------------------------------------------------------------------
extern "C" void kernel_launch(void* const* d_in, const int* in_sizes, int n_in,
                              void* d_out, int out_size)
{
    const float *x = nullptr, *wqkv = nullptr, *wproj = nullptr, *bias = nullptr;
    for (int i = 0; i < n_in; ++i) {
        switch (in_sizes[i]) {
            case 4 * 2048 * 1024: x     = (const float*)d_in[i]; break;
            case 3 * 1024 * 1024: wqkv  = (const float*)d_in[i]; break;
            case 1024 * 1024:     wproj = (const float*)d_in[i]; break;
            case 1024:            bias  = (const float*)d_in[i]; break;
        }
    }
    if (!x || !wqkv || !wproj || !bias) {
        x = (const float*)d_in[0];
        wqkv = (const float*)d_in[1];
        wproj = (const float*)d_in[2];
        bias = (const float*)d_in[3];
    }

    uint32_t *x32, *wqkv32, *wproj32, *qkv_buf, *attn_buf;
    cudaGetSymbolAddress((void**)&x32, g_x32);
    cudaGetSymbolAddress((void**)&wqkv32, g_wqkv32);
    cudaGetSymbolAddress((void**)&wproj32, g_wproj32);
    cudaGetSymbolAddress((void**)&qkv_buf, g_qkv);
    cudaGetSymbolAddress((void**)&attn_buf, g_attn);
    float* out = (float*)d_out;

    constexpr int M = 4 * 2048;  // 8192 tokens

    // 0) one-time tf32 conversion of all GEMM inputs
    cvt_kernel<<<1184, 256>>>((const float4*)x, (uint4*)x32, (4 * 2048 * 1024) / 4);
    cvt_kernel<<<592, 256>>>((const float4*)wqkv, (uint4*)wqkv32, (3 * 1024 * 1024) / 4);
    cvt_kernel<<<296, 256>>>((const float4*)wproj, (uint4*)wproj32, (1024 * 1024) / 4);

    // 1) qkv = x @ W_qkv^T  [8192, 3072] as tf32 bits, Q pre-scaled 0.125
    cudaFuncSetAttribute(gemm_kernel<0>, cudaFuncAttributeMaxDynamicSharedMemorySize, GEMM_SMEM);
    gemm_kernel<0><<<dim3(3072 / BN, M / BM), 256, GEMM_SMEM>>>(
        x32, wqkv32, nullptr, qkv_buf, M, 3072, 1024);

    // 2) flash attention -> g_attn [8192, 1024] tf32 bits
    const int smem = SMEM_U32 * 4;  // 106496 bytes
    cudaFuncSetAttribute(attn_kernel, cudaFuncAttributeMaxDynamicSharedMemorySize, smem);
    attn_kernel<<<dim3(16, 64), 256, smem>>>(qkv_buf, attn_buf);

    // 3) out = attn @ W_proj^T + b  (fp32)
    cudaFuncSetAttribute(gemm_kernel<1>, cudaFuncAttributeMaxDynamicSharedMemorySize, GEMM_SMEM);
    gemm_kernel<1><<<dim3(1024 / BN, M / BM), 256, GEMM_SMEM>>>(
        attn_buf, wproj32, bias, out, M, 1024, 1024);
    (void)out_size;
}